// round 16
// baseline (speedup 1.0000x reference)
#include <cuda_runtime.h>
#include <math.h>

// ---------------------------------------------------------------------------
// AvULoss, R16 = R12 layout x R15 math core:
//   - 256 threads/block, 128-row 16KB swizzled cp.async tile, row per PAIR
//   - no-max-subtract packed f32x2 core, consume float4 straight from LDS
//   t = x*log2e (packed); e = 2^t; S = sum e; dot = sum e*t; mt = max t
//   unc = ln2*(lg2 S - dot/S); conf = 2^mt / S; accurate: f_lab*log2e == mt
// ---------------------------------------------------------------------------

__device__ double       g_acc[2];
__device__ unsigned int g_done = 0;

#define LOG2E 1.4426950408889634f
#define LN2   0.6931471805599453f
#define TPB   256
#define ROWS  128                     // rows per block

__device__ __forceinline__ unsigned long long pk2(float lo, float hi) {
    unsigned long long r;
    asm("mov.b64 %0, {%1,%2};" : "=l"(r) : "f"(lo), "f"(hi));
    return r;
}
__device__ __forceinline__ void upk2(unsigned long long v, float& lo, float& hi) {
    asm("mov.b64 {%0,%1}, %2;" : "=f"(lo), "=f"(hi) : "l"(v));
}
__device__ __forceinline__ unsigned long long mul2(unsigned long long a,
                                                   unsigned long long b) {
    unsigned long long r;
    asm("mul.rn.f32x2 %0, %1, %2;" : "=l"(r) : "l"(a), "l"(b));
    return r;
}
__device__ __forceinline__ unsigned long long fma2(unsigned long long a,
                                                   unsigned long long b,
                                                   unsigned long long c) {
    unsigned long long r;
    asm("fma.rn.f32x2 %0, %1, %2, %3;" : "=l"(r) : "l"(a), "l"(b), "l"(c));
    return r;
}
__device__ __forceinline__ unsigned long long add2(unsigned long long a,
                                                   unsigned long long b) {
    unsigned long long r;
    asm("add.rn.f32x2 %0, %1, %2;" : "=l"(r) : "l"(a), "l"(b));
    return r;
}
__device__ __forceinline__ float ex2f(float x) {
    float r; asm("ex2.approx.f32 %0, %1;" : "=f"(r) : "f"(x)); return r;
}
__device__ __forceinline__ float lg2f(float x) {
    float r; asm("lg2.approx.f32 %0, %1;" : "=f"(r) : "f"(x)); return r;
}
__device__ __forceinline__ float rcpf(float x) {
    float r; asm("rcp.approx.f32 %0, %1;" : "=f"(r) : "f"(x)); return r;
}
__device__ __forceinline__ float tanhf_hw(float x) {
    float r; asm("tanh.approx.f32 %0, %1;" : "=f"(r) : "f"(x)); return r;
}
__device__ __forceinline__ unsigned int smem_u32(const void* p) {
    unsigned int a;
    asm("{ .reg .u64 t; cvta.to.shared.u64 t, %1; cvt.u32.u64 %0, t; }"
        : "=r"(a) : "l"(p));
    return a;
}

#define CPA(OFF) \
    asm volatile("cp.async.cg.shared.global [%0+" OFF "], [%1+" OFF "], 16;" \
                 :: "r"(dst_w), "l"(src_g) : "memory")

// consume float4 i straight from swizzled smem: packed t, exp, accum, max
#define STEP(I) { float4 v; \
    asm("ld.shared.v4.f32 {%0,%1,%2,%3}, [%4];" \
        : "=f"(v.x), "=f"(v.y), "=f"(v.z), "=f"(v.w) : "r"(rb ^ (I << 4))); \
    unsigned long long ta = mul2(pk2(v.x, v.y), L2E2); \
    unsigned long long tb = mul2(pk2(v.z, v.w), L2E2); \
    float a0, a1, b0, b1; upk2(ta, a0, a1); upk2(tb, b0, b1); \
    unsigned long long ea = pk2(ex2f(a0), ex2f(a1)); \
    unsigned long long eb = pk2(ex2f(b0), ex2f(b1)); \
    S2 = add2(S2, add2(ea, eb)); \
    D2 = fma2(ea, ta, fma2(eb, tb, D2)); \
    mt = fmaxf(mt, fmaxf(fmaxf(a0, a1), fmaxf(b0, b1))); }

__global__ __launch_bounds__(TPB, 8)
void avu_fused(const float* __restrict__ logits,
               const int*   __restrict__ labels32,
               const float* __restrict__ unc_th_p,
               int N, float* __restrict__ out)
{
    __shared__ float sdata[ROWS * 32];   // 16KB swizzled tile
    __shared__ float smr[2][TPB / 32];
    __shared__ int   s_lab64;
    __shared__ float s_th;
    __shared__ unsigned int s_rank;
    const int t   = threadIdx.x;
    const int bid = blockIdx.x;

    // ---- Label layout probe, warp-parallel (int64 => odd LE words all 0) ----
    if (t < 32) {
        int w = labels32[2 * t + 1];
        unsigned vote = __ballot_sync(0xffffffffu, w == 0);
        if (t == 0) {
            s_lab64 = (vote == 0xffffffffu);
            s_th    = unc_th_p[0];
        }
    }

    // ---- Stage 128 rows via cp.async (4 per thread), swizzled (R12). ----
    // element g = t + 256*i: r = (t>>3) + 32*i, c = t&7, r&7 = (t>>3)&7
    const unsigned int sbase = smem_u32(sdata);
    const size_t base4  = (size_t)bid * (ROWS * 8);   // float4 units
    const size_t total4 = (size_t)N * 8;
    {
        const unsigned int dst_w = sbase + ((t >> 3) << 7)
            + ((((unsigned)t & 7u) ^ (((unsigned)t >> 3) & 7u)) << 4);
        const float4* src_g = reinterpret_cast<const float4*>(logits) + base4 + t;
        if (base4 + ROWS * 8 <= total4) {
            CPA("0"); CPA("4096"); CPA("8192"); CPA("12288");
        } else {
            #pragma unroll
            for (int i = 0; i < 4; i++)
                if (base4 + (size_t)(i * TPB + t) < total4)
                    asm volatile("cp.async.cg.shared.global [%0], [%1], 16;"
                                 :: "r"(dst_w + i * 4096),
                                    "l"(src_g + (size_t)i * TPB) : "memory");
        }
    }
    asm volatile("cp.async.commit_group;" ::: "memory");
    asm volatile("cp.async.wait_group 0;" ::: "memory");
    __syncthreads();

    // ---- Compute: thread pair (2k, 2k+1) handles row k; h = half. ----
    const int r     = t >> 1;
    const int h     = t & 1;
    const int row   = bid * ROWS + r;
    const bool valid = row < N;
    const int rowc  = valid ? row : 0;
    const int lab   = s_lab64 ? labels32[2 * (size_t)rowc]
                              : labels32[(size_t)rowc];

    // half-row read base (swizzle phase folded in; R12 derivation):
    // addr(i) = rb ^ (i<<4)
    const unsigned int rb = (sbase + ((unsigned)r << 7)
        + (((unsigned)(h ^ ((r >> 2) & 1))) << 6))
        | (((unsigned)r & 3u) << 4);

    const unsigned long long L2E2 = pk2(LOG2E, LOG2E);
    unsigned long long S2 = 0ull, D2 = 0ull;
    float mt = -1e30f;
    STEP(0u) STEP(1u) STEP(2u) STEP(3u)

    float sl, sh2, dl, dh;
    upk2(S2, sl, sh2); upk2(D2, dl, dh);
    float S   = sl + sh2;
    float dot = dl + dh;

    // pair combine: 3 shuffles
    mt   = fmaxf(mt, __shfl_xor_sync(0xffffffffu, mt, 1));
    S   += __shfl_xor_sync(0xffffffffu, S,   1);
    dot += __shfl_xor_sync(0xffffffffu, dot, 1);

    const float rcpS = rcpf(S);
    const float unc  = LN2 * (lg2f(S) - dot * rcpS);   // entropy
    const float conf = ex2f(mt) * rcpS;                // max prob
    const float tn   = tanhf_hw(unc);

    // f[label] from tile (full-row addressing); compare in t-space
    float fl;
    asm("ld.shared.f32 %0, [%1];"
        : "=f"(fl)
        : "r"(sbase + ((unsigned)r << 7)
              + ((((unsigned)(lab >> 2) ^ ((unsigned)r & 7u))) << 4)
              + (((unsigned)lab & 3u) << 2)));
    const bool accurate = (fl * LOG2E == mt);          // ties measure-zero
    const bool certain  = (unc <= s_th);

    float d = (accurate ? conf : 1.0f - conf) * (certain ? 1.0f - tn : tn);
    float c_den = valid ? d : 0.f;
    float c_num = (valid & (accurate == certain)) ? d : 0.f;   // AC + IU

    // ---- Warp butterfly + block reduce (halves counted twice -> x0.5) ----
    #pragma unroll
    for (int o = 16; o > 0; o >>= 1) {
        c_num += __shfl_xor_sync(0xffffffffu, c_num, o);
        c_den += __shfl_xor_sync(0xffffffffu, c_den, o);
    }
    const int wid = t >> 5, lid = t & 31;
    if (lid == 0) { smr[0][wid] = c_num; smr[1][wid] = c_den; }
    __syncthreads();
    if (t < 2) {
        float s = 0.f;
        #pragma unroll
        for (int i = 0; i < TPB / 32; i++) s += smr[t][i];
        atomicAdd(&g_acc[t], (double)(s * 0.5f));
    }

    // ---- Last-block finish + self-reset (graph-replay safe) ----
    __threadfence();
    __syncthreads();
    if (t == 0) s_rank = atomicAdd(&g_done, 1u);
    __syncthreads();
    if (t == 0 && s_rank == gridDim.x - 1) {
        __threadfence();
        double num = atomicAdd(&g_acc[0], 0.0);
        double den = atomicAdd(&g_acc[1], 0.0);
        double avu = num / (den + 1e-10);
        out[0] = (float)(-log(avu + 1e-10));
        g_acc[0] = 0.0; g_acc[1] = 0.0;
        __threadfence();
        g_done = 0u;
    }
}

extern "C" void kernel_launch(void* const* d_in, const int* in_sizes, int n_in,
                              void* d_out, int out_size)
{
    const float* logits = (const float*)d_in[0];
    const int*   labels = (const int*)  d_in[1];
    const float* unc_th = (const float*)d_in[2];
    const int N = in_sizes[1];

    avu_fused<<<(N + ROWS - 1) / ROWS, TPB>>>(logits, labels, unc_th, N,
                                              (float*)d_out);
}

// round 17
// speedup vs baseline: 1.0984x; 1.0984x over previous
#include <cuda_runtime.h>
#include <math.h>

// ---------------------------------------------------------------------------
// AvULoss, R17 = R15 math core + warp-autonomous staging:
//   - 256 thr/block, 32KB tile; warp w owns rows [32w,32w+32) = private 4KB
//   - warp stages its own rows (8 x 512B coalesced cp.async), waits only on
//     itself (wait_group 0 + syncwarp) -> no block barrier in hot path
//   - full row per thread, no-max-subtract packed f32x2 consume-from-LDS
//   t = x*log2e; e = 2^t; S = sum e; dot = sum e*t; mt = max t
//   unc = ln2*(lg2 S - dot/S); conf = 2^mt/S; accurate: f_lab*log2e == mt
// ---------------------------------------------------------------------------

__device__ double       g_acc[2];
__device__ unsigned int g_done = 0;

#define LOG2E 1.4426950408889634f
#define LN2   0.6931471805599453f
#define TPB   256
#define ROWS  256                     // rows per block (1 per thread)

__device__ __forceinline__ unsigned long long pk2(float lo, float hi) {
    unsigned long long r;
    asm("mov.b64 %0, {%1,%2};" : "=l"(r) : "f"(lo), "f"(hi));
    return r;
}
__device__ __forceinline__ void upk2(unsigned long long v, float& lo, float& hi) {
    asm("mov.b64 {%0,%1}, %2;" : "=f"(lo), "=f"(hi) : "l"(v));
}
__device__ __forceinline__ unsigned long long mul2(unsigned long long a,
                                                   unsigned long long b) {
    unsigned long long r;
    asm("mul.rn.f32x2 %0, %1, %2;" : "=l"(r) : "l"(a), "l"(b));
    return r;
}
__device__ __forceinline__ unsigned long long fma2(unsigned long long a,
                                                   unsigned long long b,
                                                   unsigned long long c) {
    unsigned long long r;
    asm("fma.rn.f32x2 %0, %1, %2, %3;" : "=l"(r) : "l"(a), "l"(b), "l"(c));
    return r;
}
__device__ __forceinline__ unsigned long long add2(unsigned long long a,
                                                   unsigned long long b) {
    unsigned long long r;
    asm("add.rn.f32x2 %0, %1, %2;" : "=l"(r) : "l"(a), "l"(b));
    return r;
}
__device__ __forceinline__ float ex2f(float x) {
    float r; asm("ex2.approx.f32 %0, %1;" : "=f"(r) : "f"(x)); return r;
}
__device__ __forceinline__ float lg2f(float x) {
    float r; asm("lg2.approx.f32 %0, %1;" : "=f"(r) : "f"(x)); return r;
}
__device__ __forceinline__ float rcpf(float x) {
    float r; asm("rcp.approx.f32 %0, %1;" : "=f"(r) : "f"(x)); return r;
}
__device__ __forceinline__ float tanhf_hw(float x) {
    float r; asm("tanh.approx.f32 %0, %1;" : "=f"(r) : "f"(x)); return r;
}
__device__ __forceinline__ unsigned int smem_u32(const void* p) {
    unsigned int a;
    asm("{ .reg .u64 t; cvta.to.shared.u64 t, %1; cvt.u32.u64 %0, t; }"
        : "=r"(a) : "l"(p));
    return a;
}

// cp.async: dst reg + literal offset, src reg + matching element offset
#define CPW(BASE, OFF, IDX) \
    asm volatile("cp.async.cg.shared.global [%0+" OFF "], [%1], 16;" \
                 :: "r"(BASE), "l"(src_g + (IDX) * 32) : "memory")

// consume float4 j straight from swizzled smem: packed t, exp, accum, max
#define STEP(J) { float4 v; \
    asm("ld.shared.v4.f32 {%0,%1,%2,%3}, [%4];" \
        : "=f"(v.x), "=f"(v.y), "=f"(v.z), "=f"(v.w) : "r"(rb ^ (J << 4))); \
    unsigned long long ta = mul2(pk2(v.x, v.y), L2E2); \
    unsigned long long tb = mul2(pk2(v.z, v.w), L2E2); \
    float a0, a1, b0, b1; upk2(ta, a0, a1); upk2(tb, b0, b1); \
    unsigned long long ea = pk2(ex2f(a0), ex2f(a1)); \
    unsigned long long eb = pk2(ex2f(b0), ex2f(b1)); \
    S2 = add2(S2, add2(ea, eb)); \
    D2 = fma2(ea, ta, fma2(eb, tb, D2)); \
    mt = fmaxf(mt, fmaxf(fmaxf(a0, a1), fmaxf(b0, b1))); }

__global__ __launch_bounds__(TPB, 7)
void avu_fused(const float* __restrict__ logits,
               const int*   __restrict__ labels32,
               const float* __restrict__ unc_th_p,
               int N, float* __restrict__ out)
{
    __shared__ float sdata[ROWS * 32];   // 32KB: 8 warp-private 4KB slices
    __shared__ float smr[2][TPB / 32];
    __shared__ unsigned int s_rank;
    const int t   = threadIdx.x;
    const int bid = blockIdx.x;
    const int w   = t >> 5;              // warp id
    const int l   = t & 31;              // lane

    // ---- Per-warp label-layout probe, register-only (no smem, no sync). ----
    // int64 labels (<32) => odd LE words of first 64 words are all zero.
    int lab64;
    {
        int wv = labels32[2 * l + 1];
        lab64 = (__ballot_sync(0xffffffffu, wv == 0) == 0xffffffffu);
    }
    const float th = unc_th_p[0];        // uniform load, L1 broadcast

    // ---- Warp-autonomous staging: rows [bid*256 + 32w, +32) -> 4KB slice ----
    // lane l, iter i loads warp-f4 g = 32i + l; row = 4i + (l>>3), c = l&7.
    // swizzled dst = slice + row*128 + ((c ^ (row&7))<<4)
    //   row&7 = 4(i&1) | (l>>3)  =>  dst(i) = (A0 ^ ((i&1)<<6)) + i*512
    const unsigned int slice = smem_u32(sdata) + ((unsigned)w << 12);
    const size_t rowbase = (size_t)bid * ROWS + (unsigned)(w << 5);
    {
        const unsigned int A0 = slice + (((unsigned)l >> 3) << 7)
            + (((((unsigned)l & 7u)) ^ ((unsigned)l >> 3)) << 4);
        const unsigned int A1 = A0 ^ 64u;
        const float4* src_g = reinterpret_cast<const float4*>(logits)
                            + rowbase * 8 + l;
        if (rowbase + 32 <= (size_t)N) {
            CPW(A0, "0",    0); CPW(A1, "512",  1);
            CPW(A0, "1024", 2); CPW(A1, "1536", 3);
            CPW(A0, "2048", 4); CPW(A1, "2560", 5);
            CPW(A0, "3072", 6); CPW(A1, "3584", 7);
        } else {
            #pragma unroll
            for (int i = 0; i < 8; i++)
                if (rowbase * 8 + (size_t)(32 * i + l) < (size_t)N * 8)
                    asm volatile("cp.async.cg.shared.global [%0], [%1], 16;"
                                 :: "r"(((i & 1) ? A1 : A0) + i * 512),
                                    "l"(src_g + (size_t)i * 32) : "memory");
        }
    }
    asm volatile("cp.async.commit_group;" ::: "memory");
    asm volatile("cp.async.wait_group 0;" ::: "memory");
    __syncwarp();

    // ---- Compute: lane l owns warp row l. ----
    const size_t row   = rowbase + (unsigned)l;
    const bool   valid = row < (size_t)N;
    float c_num = 0.f, c_den = 0.f;
    if (valid) {
        const int lab = lab64 ? labels32[2 * row] : labels32[row];
        // row read base with swizzle phase folded in: addr(j) = rb ^ (j<<4)
        const unsigned int rb = (slice + ((unsigned)l << 7))
                              | (((unsigned)l & 7u) << 4);

        const unsigned long long L2E2 = pk2(LOG2E, LOG2E);
        unsigned long long S2 = 0ull, D2 = 0ull;
        float mt = -1e30f;
        STEP(0u) STEP(1u) STEP(2u) STEP(3u)
        STEP(4u) STEP(5u) STEP(6u) STEP(7u)

        float sl, sh, dl, dh;
        upk2(S2, sl, sh); upk2(D2, dl, dh);
        const float S   = sl + sh;
        const float dot = dl + dh;

        const float rcpS = rcpf(S);
        const float unc  = LN2 * (lg2f(S) - dot * rcpS);  // entropy
        const float conf = ex2f(mt) * rcpS;               // max prob
        const float tn   = tanhf_hw(unc);

        float fl;
        asm("ld.shared.f32 %0, [%1];"
            : "=f"(fl)
            : "r"((rb ^ (((unsigned)lab >> 2) << 4)) + (((unsigned)lab & 3u) << 2)));
        const bool accurate = (fl * LOG2E == mt);         // ties measure-zero
        const bool certain  = (unc <= th);

        c_den = (accurate ? conf : 1.0f - conf) * (certain ? 1.0f - tn : tn);
        c_num = (accurate == certain) ? c_den : 0.f;      // AC + IU
    }

    // ---- Warp butterfly + block reduce (single block barrier). ----
    #pragma unroll
    for (int o = 16; o > 0; o >>= 1) {
        c_num += __shfl_xor_sync(0xffffffffu, c_num, o);
        c_den += __shfl_xor_sync(0xffffffffu, c_den, o);
    }
    if (l == 0) { smr[0][w] = c_num; smr[1][w] = c_den; }
    __syncthreads();
    if (t < 2) {
        float s = 0.f;
        #pragma unroll
        for (int i = 0; i < TPB / 32; i++) s += smr[t][i];
        atomicAdd(&g_acc[t], (double)s);
    }

    // ---- Last-block finish + self-reset (graph-replay safe) ----
    __threadfence();
    __syncthreads();
    if (t == 0) s_rank = atomicAdd(&g_done, 1u);
    __syncthreads();
    if (t == 0 && s_rank == gridDim.x - 1) {
        __threadfence();
        double num = atomicAdd(&g_acc[0], 0.0);
        double den = atomicAdd(&g_acc[1], 0.0);
        double avu = num / (den + 1e-10);
        out[0] = (float)(-log(avu + 1e-10));
        g_acc[0] = 0.0; g_acc[1] = 0.0;
        __threadfence();
        g_done = 0u;
    }
}

extern "C" void kernel_launch(void* const* d_in, const int* in_sizes, int n_in,
                              void* d_out, int out_size)
{
    const float* logits = (const float*)d_in[0];
    const int*   labels = (const int*)  d_in[1];
    const float* unc_th = (const float*)d_in[2];
    const int N = in_sizes[1];

    avu_fused<<<(N + ROWS - 1) / ROWS, TPB>>>(logits, labels, unc_th, N,
                                              (float*)d_out);
}